// round 5
// baseline (speedup 1.0000x reference)
#include <cuda_runtime.h>
#include <cuda_bf16.h>
#include <cuda_fp16.h>
#include <cstdint>

#define D 64
#define MAX_N 100000
#define MAX_E 1200000
#define SCAN_BLK 1024

// ---------------------------------------------------------------------------
// Scratch (device globals — no allocation allowed)
// ---------------------------------------------------------------------------
__device__ __nv_bfloat16 g_aggh[MAX_N * D];  // agg mean, bf16 hi
__device__ __nv_bfloat16 g_aggl[MAX_N * D];  // agg mean, bf16 lo
__device__ __nv_bfloat16 g_xh[MAX_N * D];    // x hi
__device__ __nv_bfloat16 g_xl[MAX_N * D];    // x lo
__device__ __half        g_x16[MAX_N * D];   // x fp16 (gather copy)
__device__ __nv_bfloat16 g_hh[MAX_N * D];    // h hi
__device__ __nv_bfloat16 g_hl[MAX_N * D];    // h lo
__device__ __half        g_h16[MAX_N * D];   // h fp16 (gather copy)
__device__ int   g_cnt[MAX_N];
__device__ int   g_off[MAX_N + 1];
__device__ int   g_cur[MAX_N];
__device__ int   g_part[128];
__device__ int   g_ccol[MAX_E];
__device__ __nv_bfloat16 g_Wh[2][64 * 128];  // [layer][n*128+k]  W^T hi
__device__ __nv_bfloat16 g_Wl[2][64 * 128];  // [layer][n*128+k]  W^T lo

// ---------------------------------------------------------------------------
// PTX helpers — BASE ISA ONLY (harness compiles at .target sm_103, no 'a')
// ---------------------------------------------------------------------------
__device__ __forceinline__ uint32_t smem_u32(const void* p) {
    uint32_t a;
    asm("{ .reg .u64 t; cvta.to.shared.u64 t, %1; cvt.u32.u64 %0, t; }"
        : "=r"(a) : "l"(p));
    return a;
}
__device__ __forceinline__ void ldsm_x4(uint32_t& r0, uint32_t& r1,
                                        uint32_t& r2, uint32_t& r3,
                                        uint32_t addr) {
    asm volatile("ldmatrix.sync.aligned.m8n8.x4.shared.b16 {%0,%1,%2,%3}, [%4];"
                 : "=r"(r0), "=r"(r1), "=r"(r2), "=r"(r3) : "r"(addr));
}
__device__ __forceinline__ void mma_bf16(float* c, const uint32_t* a,
                                         uint32_t b0, uint32_t b1) {
    asm volatile(
        "mma.sync.aligned.m16n8k16.row.col.f32.bf16.bf16.f32 "
        "{%0,%1,%2,%3}, {%4,%5,%6,%7}, {%8,%9}, {%0,%1,%2,%3};"
        : "+f"(c[0]), "+f"(c[1]), "+f"(c[2]), "+f"(c[3])
        : "r"(a[0]), "r"(a[1]), "r"(a[2]), "r"(a[3]), "r"(b0), "r"(b1));
}
__device__ __forceinline__ uint32_t pack_bf2(float x, float y) {
    __nv_bfloat162 p(__float2bfloat16(x), __float2bfloat16(y));
    return *(uint32_t*)&p;
}

// ---------------------------------------------------------------------------
// Input prep: x -> hi/lo bf16 + fp16 gather copy
// ---------------------------------------------------------------------------
__global__ void prep_x_kernel(const float* __restrict__ x, int N) {
    int i = blockIdx.x * blockDim.x + threadIdx.x;   // float4 granules
    int tot = N * (D / 4);
    if (i >= tot) return;
    float4 v = ((const float4*)x)[i];
    __nv_bfloat16 h0 = __float2bfloat16(v.x), h1 = __float2bfloat16(v.y);
    __nv_bfloat16 h2 = __float2bfloat16(v.z), h3 = __float2bfloat16(v.w);
    uint2 hv = make_uint2(pack_bf2(v.x, v.y), pack_bf2(v.z, v.w));
    uint2 lv = make_uint2(
        pack_bf2(v.x - __bfloat162float(h0), v.y - __bfloat162float(h1)),
        pack_bf2(v.z - __bfloat162float(h2), v.w - __bfloat162float(h3)));
    __half2 f0 = __floats2half2_rn(v.x, v.y);
    __half2 f1 = __floats2half2_rn(v.z, v.w);
    ((uint2*)g_xh)[i] = hv;
    ((uint2*)g_xl)[i] = lv;
    ((uint2*)g_x16)[i] = make_uint2(*(uint32_t*)&f0, *(uint32_t*)&f1);
}

// ---------------------------------------------------------------------------
// Weight prep: split W[k][n] fp32 -> Wh/Wl bf16, transposed to [n][k] K-major
// ---------------------------------------------------------------------------
__global__ void prep_w_kernel(const float* __restrict__ W1,
                              const float* __restrict__ W2) {
    int i = blockIdx.x * blockDim.x + threadIdx.x;
    if (i >= 2 * 8192) return;
    int layer = i >> 13;
    int j = i & 8191;           // j = k*64 + n
    int k = j >> 6;
    int n = j & 63;
    float w = (layer ? W2 : W1)[j];
    __nv_bfloat16 h = __float2bfloat16(w);
    float lo = w - __bfloat162float(h);
    g_Wh[layer][n * 128 + k] = h;
    g_Wl[layer][n * 128 + k] = __float2bfloat16(lo);
}

// ---------------------------------------------------------------------------
// CSR build
// ---------------------------------------------------------------------------
__global__ void zero_cnt_kernel(int n) {
    int i = blockIdx.x * blockDim.x + threadIdx.x;
    if (i < n) g_cnt[i] = 0;
}
__global__ void hist_kernel(const int* __restrict__ row, int E) {
    int e = blockIdx.x * blockDim.x + threadIdx.x;
    if (e < E) atomicAdd(&g_cnt[row[e]], 1);
}
// Block-local exclusive scan via warp shuffles; block totals -> g_part
__global__ void scan1_kernel(int n) {
    __shared__ int wsum[32];
    int tid = threadIdx.x, lane = tid & 31, w = tid >> 5;
    int i = blockIdx.x * SCAN_BLK + tid;
    int v = (i < n) ? g_cnt[i] : 0;
    int s = v;
#pragma unroll
    for (int o = 1; o < 32; o <<= 1) {
        int t = __shfl_up_sync(0xFFFFFFFFu, s, o);
        if (lane >= o) s += t;
    }
    if (lane == 31) wsum[w] = s;
    __syncthreads();
    if (w == 0) {
        int t = wsum[lane];
        int ts = t;
#pragma unroll
        for (int o = 1; o < 32; o <<= 1) {
            int u = __shfl_up_sync(0xFFFFFFFFu, ts, o);
            if (lane >= o) ts += u;
        }
        wsum[lane] = ts - t;
    }
    __syncthreads();
    int incl = s + wsum[w];
    if (i < n) g_off[i] = incl - v;    // block-local exclusive
    if (tid == SCAN_BLK - 1) g_part[blockIdx.x] = incl;
}
// Fused: each block computes its own base from g_part, adds, inits cursors
__global__ void scan3_kernel(int n, int E) {
    __shared__ int sred[4];
    __shared__ int sbase;
    int tid = threadIdx.x, lane = tid & 31, w = tid >> 5;
    if (tid < 128) {
        int v = (tid < blockIdx.x) ? g_part[tid] : 0;
#pragma unroll
        for (int o = 16; o > 0; o >>= 1)
            v += __shfl_down_sync(0xFFFFFFFFu, v, o);
        if (lane == 0) sred[w] = v;
    }
    __syncthreads();
    if (tid == 0) sbase = sred[0] + sred[1] + sred[2] + sred[3];
    __syncthreads();
    int base = sbase;
    int i = blockIdx.x * SCAN_BLK + tid;
    if (i < n) {
        int v = g_off[i] + base;
        g_off[i] = v;
        g_cur[i] = v;
    }
    if (i == 0) g_off[n] = E;
}
__global__ void fill_kernel(const int* __restrict__ row,
                            const int* __restrict__ col, int E) {
    int e = blockIdx.x * blockDim.x + threadIdx.x;
    if (e < E) {
        int pos = atomicAdd(&g_cur[row[e]], 1);
        g_ccol[pos] = col[e];
    }
}

// ---------------------------------------------------------------------------
// Aggregate: one warp per node; gather fp16 rows (128B), fp32 accumulate,
// write mean pre-split as bf16 hi/lo.
// ---------------------------------------------------------------------------
__global__ void aggregate_kernel(const __half* __restrict__ src16, int N) {
    int gw = (blockIdx.x * blockDim.x + threadIdx.x) >> 5;
    if (gw >= N) return;
    int lane = threadIdx.x & 31;
    int beg = g_off[gw];
    int end = g_off[gw + 1];
    float ax = 0.f, ay = 0.f;
#pragma unroll 8
    for (int i = beg; i < end; i++) {
        int c = __ldg(&g_ccol[i]);
        __half2 v = ((const __half2*)(src16 + (size_t)c * D))[lane];
        float2 f = __half22float2(v);
        ax += f.x;
        ay += f.y;
    }
    float inv = 1.0f / fmaxf((float)(end - beg), 1.0f);
    ax *= inv;
    ay *= inv;
    __nv_bfloat16 hx = __float2bfloat16(ax), hy = __float2bfloat16(ay);
    uint32_t hp;
    { __nv_bfloat162 t(hx, hy); hp = *(uint32_t*)&t; }
    uint32_t lp = pack_bf2(ax - __bfloat162float(hx), ay - __bfloat162float(hy));
    ((uint32_t*)(g_aggh + (size_t)gw * D))[lane] = hp;
    ((uint32_t*)(g_aggl + (size_t)gw * D))[lane] = lp;
}

// ---------------------------------------------------------------------------
// GEMM via mma.sync (HMMA): out[128-node tile][64] =
//   concat(self, agg)[128][128] @ W + b,  bf16 3-pass split, fp32 accum.
// All inputs pre-split bf16 -> staging is pure copy.
// mode 0: write fp32 out.  mode 1: write h split (hh, hl, h16) + relu.
// ---------------------------------------------------------------------------
#define APAD 136
#define SM_A_ELEMS (128 * APAD)
#define SM_W_ELEMS (64 * APAD)
#define SM_GEMM (256 + 2 * SM_A_ELEMS * 2 + 2 * SM_W_ELEMS * 2)

__global__ void __launch_bounds__(256, 1)
gemm_kernel(const __nv_bfloat16* __restrict__ selfh,
            const __nv_bfloat16* __restrict__ selfl,
            const float* __restrict__ bias, float* __restrict__ outF,
            int N, int mode, int layer) {
    extern __shared__ char smem[];
    float* bs = (float*)smem;
    __nv_bfloat16* Ah = (__nv_bfloat16*)(smem + 256);
    __nv_bfloat16* Al = Ah + SM_A_ELEMS;
    __nv_bfloat16* Wh = Al + SM_A_ELEMS;
    __nv_bfloat16* Wl = Wh + SM_W_ELEMS;

    int tid = threadIdx.x;
    int lane = tid & 31;
    int wid = tid >> 5;
    int node0 = blockIdx.x * 128;

    if (tid < 64) bs[tid] = bias[tid];

    // --- Stage W ---
    const __nv_bfloat16* gWh = g_Wh[layer];
    const __nv_bfloat16* gWl = g_Wl[layer];
#pragma unroll
    for (int it = 0; it < 8; it++) {
        int g = it * 256 + tid;
        int n = g >> 5;
        int k = (g & 31) * 4;
        *(uint2*)(Wh + n * APAD + k) = *(const uint2*)(gWh + n * 128 + k);
        *(uint2*)(Wl + n * APAD + k) = *(const uint2*)(gWl + n * 128 + k);
    }

    // --- Stage A (pure copies; k<64 self, k>=64 agg) ---
#pragma unroll
    for (int it = 0; it < 16; it++) {
        int g = it * 256 + tid;            // 4096 granules of 4 bf16
        int row = g >> 5;
        int seg = g & 31;
        int node = node0 + row;
        uint2 hv = make_uint2(0u, 0u), lv = make_uint2(0u, 0u);
        if (node < N) {
            if (seg < 16) {
                hv = *(const uint2*)(selfh + (size_t)node * D + seg * 4);
                lv = *(const uint2*)(selfl + (size_t)node * D + seg * 4);
            } else {
                hv = *(const uint2*)(g_aggh + (size_t)node * D + (seg - 16) * 4);
                lv = *(const uint2*)(g_aggl + (size_t)node * D + (seg - 16) * 4);
            }
        }
        int k = seg * 4;
        *(uint2*)(Ah + row * APAD + k) = hv;
        *(uint2*)(Al + row * APAD + k) = lv;
    }
    __syncthreads();

    // --- MMA: warp w -> rows [16w, 16w+16), all 64 cols ---
    int r0 = 16 * wid;
    float c[8][4];
#pragma unroll
    for (int a = 0; a < 8; a++)
#pragma unroll
        for (int j = 0; j < 4; j++) c[a][j] = 0.f;

    uint32_t aBaseH = smem_u32(Ah);
    uint32_t aBaseL = smem_u32(Al);
    uint32_t wBaseH = smem_u32(Wh);
    uint32_t wBaseL = smem_u32(Wl);
    uint32_t aRowOff = (uint32_t)((r0 + (lane & 15)) * APAD + 8 * (lane >> 4)) * 2;
    uint32_t wRowOff = (uint32_t)(((lane & 7) + 8 * ((lane >> 4) & 1)) * APAD +
                                  8 * ((lane >> 3) & 1)) * 2;

#pragma unroll
    for (int kk = 0; kk < 8; kk++) {
        uint32_t kOff = (uint32_t)(16 * kk) * 2;
        uint32_t ah[4], al[4];
        ldsm_x4(ah[0], ah[1], ah[2], ah[3], aBaseH + aRowOff + kOff);
        ldsm_x4(al[0], al[1], al[2], al[3], aBaseL + aRowOff + kOff);
#pragma unroll
        for (int g = 0; g < 4; g++) {
            uint32_t nOff = (uint32_t)(16 * g * APAD) * 2;
            uint32_t bh0, bh1, bh2, bh3, bl0, bl1, bl2, bl3;
            ldsm_x4(bh0, bh1, bh2, bh3, wBaseH + wRowOff + nOff + kOff);
            ldsm_x4(bl0, bl1, bl2, bl3, wBaseL + wRowOff + nOff + kOff);
            mma_bf16(c[2 * g],     ah, bh0, bh1);
            mma_bf16(c[2 * g],     al, bh0, bh1);
            mma_bf16(c[2 * g],     ah, bl0, bl1);
            mma_bf16(c[2 * g + 1], ah, bh2, bh3);
            mma_bf16(c[2 * g + 1], al, bh2, bh3);
            mma_bf16(c[2 * g + 1], ah, bl2, bl3);
        }
    }

    // --- Epilogue ---
    int rowa = r0 + (lane >> 2);
    int nodea = node0 + rowa;
    int nodeb = nodea + 8;
    int t2 = 2 * (lane & 3);
#pragma unroll
    for (int a = 0; a < 8; a++) {
        int col = 8 * a + t2;
        float2 bb = *(float2*)&bs[col];
#pragma unroll
        for (int half = 0; half < 2; half++) {
            int node = half ? nodeb : nodea;
            if (node >= N) continue;
            float ox = c[a][2 * half + 0] + bb.x;
            float oy = c[a][2 * half + 1] + bb.y;
            if (mode == 1) {
                ox = fmaxf(ox, 0.f);
                oy = fmaxf(oy, 0.f);
                size_t idx = (size_t)node * D + col;
                __nv_bfloat16 hx = __float2bfloat16(ox);
                __nv_bfloat16 hy = __float2bfloat16(oy);
                __nv_bfloat162 hp(hx, hy);
                *(uint32_t*)(g_hh + idx) = *(uint32_t*)&hp;
                *(uint32_t*)(g_hl + idx) =
                    pack_bf2(ox - __bfloat162float(hx), oy - __bfloat162float(hy));
                __half2 f = __floats2half2_rn(ox, oy);
                *(uint32_t*)(g_h16 + idx) = *(uint32_t*)&f;
            } else {
                *(float2*)(outF + (size_t)node * D + col) = make_float2(ox, oy);
            }
        }
    }
}

// ---------------------------------------------------------------------------
extern "C" void kernel_launch(void* const* d_in, const int* in_sizes, int n_in,
                              void* d_out, int out_size) {
    const float* x  = (const float*)d_in[0];
    const int*   ei = (const int*)d_in[1];
    const float* W1 = (const float*)d_in[2];
    const float* b1 = (const float*)d_in[3];
    const float* W2 = (const float*)d_in[4];
    const float* b2 = (const float*)d_in[5];
    int N = in_sizes[0] / D;
    int E = in_sizes[1] / 2;
    const int* row = ei;
    const int* col = ei + E;
    float* out = (float*)d_out;

    __half *x16_ptr = nullptr, *h16_ptr = nullptr;
    __nv_bfloat16 *xh_ptr = nullptr, *xl_ptr = nullptr;
    __nv_bfloat16 *hh_ptr = nullptr, *hl_ptr = nullptr;
    cudaGetSymbolAddress((void**)&x16_ptr, g_x16);
    cudaGetSymbolAddress((void**)&h16_ptr, g_h16);
    cudaGetSymbolAddress((void**)&xh_ptr, g_xh);
    cudaGetSymbolAddress((void**)&xl_ptr, g_xl);
    cudaGetSymbolAddress((void**)&hh_ptr, g_hh);
    cudaGetSymbolAddress((void**)&hl_ptr, g_hl);

    cudaFuncSetAttribute(gemm_kernel,
                         cudaFuncAttributeMaxDynamicSharedMemorySize, SM_GEMM);

    int scan_blocks = (N + SCAN_BLK - 1) / SCAN_BLK;
    int eb = (E + 255) / 256;
    int agg_blocks = (N * 32 + 255) / 256;
    int tiles = (N + 127) / 128;

    // --- Prep + CSR build ---
    prep_w_kernel<<<(2 * 8192 + 255) / 256, 256>>>(W1, W2);
    prep_x_kernel<<<(N * 16 + 255) / 256, 256>>>(x, N);
    zero_cnt_kernel<<<(N + 255) / 256, 256>>>(N);
    hist_kernel<<<eb, 256>>>(row, E);
    scan1_kernel<<<scan_blocks, SCAN_BLK>>>(N);
    scan3_kernel<<<scan_blocks, SCAN_BLK>>>(N, E);
    fill_kernel<<<eb, 256>>>(row, col, E);

    // --- Layer 1 ---
    aggregate_kernel<<<agg_blocks, 256>>>(x16_ptr, N);
    gemm_kernel<<<tiles, 256, SM_GEMM>>>(xh_ptr, xl_ptr, b1, nullptr, N, 1, 0);

    // --- Layer 2 ---
    aggregate_kernel<<<agg_blocks, 256>>>(h16_ptr, N);
    gemm_kernel<<<tiles, 256, SM_GEMM>>>(hh_ptr, hl_ptr, b2, out, N, 0, 1);
}